// round 15
// baseline (speedup 1.0000x reference)
#include <cuda_runtime.h>
#include <cstdint>

#define EPS 0.01f
#define CHUNK_ELEMS 1024
#define CHUNK_BYTES (CHUNK_ELEMS * 4)      // 4096 B per stream
#define STAGE_BYTES (3 * CHUNK_BYTES)      // 12288 B per stage, 2 stages = 24KB

__device__ float g_acc = 0.0f;           // reset by last block each run
__device__ unsigned int g_count = 0;     // reset by last block each run
__device__ unsigned int g_chunk = 0;     // reset by last block each run

__device__ __forceinline__ uint32_t smem_u32(const void* p) {
    return (uint32_t)__cvta_generic_to_shared(p);
}
__device__ __forceinline__ void mbar_init(uint32_t a, uint32_t cnt) {
    asm volatile("mbarrier.init.shared.b64 [%0], %1;" :: "r"(a), "r"(cnt) : "memory");
}
__device__ __forceinline__ void mbar_expect_tx(uint32_t a, uint32_t bytes) {
    asm volatile("mbarrier.arrive.expect_tx.shared.b64 _, [%0], %1;"
                 :: "r"(a), "r"(bytes) : "memory");
}
__device__ __forceinline__ void mbar_wait(uint32_t a, uint32_t parity) {
    uint32_t done;
    asm volatile("{\n\t.reg .pred p;\n\t"
                 "mbarrier.try_wait.parity.acquire.cta.shared::cta.b64 p, [%1], %2;\n\t"
                 "selp.b32 %0, 1, 0, p;\n\t}"
                 : "=r"(done) : "r"(a), "r"(parity) : "memory");
    if (!done) {
        asm volatile("{\n\t.reg .pred P1;\n\t"
                     "W_%=:\n\t"
                     "mbarrier.try_wait.parity.acquire.cta.shared::cta.b64 P1, [%0], %1, 0x989680;\n\t"
                     "@P1 bra.uni D_%=;\n\t"
                     "bra.uni W_%=;\n\t"
                     "D_%=:\n\t}" :: "r"(a), "r"(parity) : "memory");
    }
}
__device__ __forceinline__ void bulk_g2s(uint32_t dst, const void* src,
                                         uint32_t bytes, uint32_t mbar) {
    asm volatile("cp.async.bulk.shared::cluster.global.mbarrier::complete_tx::bytes "
                 "[%0], [%1], %2, [%3];"
                 :: "r"(dst), "l"(src), "r"(bytes), "r"(mbar) : "memory");
}

extern __shared__ __align__(16) char dynbuf[];  // 24KB: [stage0|stage1] x [pred|label|em]

__global__ void __launch_bounds__(256)
elc_tma_kernel(const float* __restrict__ pred,
               const int*   __restrict__ label,
               const float* __restrict__ Wl,
               const float* __restrict__ label_sum,
               const float* __restrict__ em,
               int n_total, int n_ls,
               float* __restrict__ out)
{
    __shared__ float sWl[16];
    __shared__ int   s_c[2];
    __shared__ __align__(8) uint64_t mb[2];
    __shared__ float red[8];
    __shared__ bool  s_last;

    const int tid = threadIdx.x;
    const int nchunks = (n_total + CHUNK_ELEMS - 1) / CHUNK_ELEMS;   // 32768

    if (tid < 16) sWl[tid] = Wl[tid];
    if (tid == 0) {
        mbar_init(smem_u32(&mb[0]), 1);
        mbar_init(smem_u32(&mb[1]), 1);
        s_c[0] = (int)atomicAdd(&g_chunk, 1u);
    }
    __syncthreads();

    float acc = 0.0f;
    int c_cur = s_c[0];
    int phase0 = 0, phase1 = 0;
    int s = 0;

    // prologue: issue first chunk into stage 0
    if (c_cur < nchunks && tid == 0) {
        const int base = c_cur * CHUNK_ELEMS;
        const uint32_t bytes = (uint32_t)min(CHUNK_ELEMS, n_total - base) * 4u;
        const uint32_t d = smem_u32(dynbuf);
        const uint32_t m = smem_u32(&mb[0]);
        mbar_expect_tx(m, 3u * bytes);
        bulk_g2s(d,                   pred  + base, bytes, m);
        bulk_g2s(d + CHUNK_BYTES,     label + base, bytes, m);
        bulk_g2s(d + 2 * CHUNK_BYTES, em    + base, bytes, m);
    }

    while (c_cur < nchunks) {
        // grab + prefetch next chunk into the other stage
        if (tid == 0) s_c[s ^ 1] = (int)atomicAdd(&g_chunk, 1u);
        __syncthreads();               // publish s_c; also: stage s^1 was fully
                                       // consumed before this point last iter
        const int c_nxt = s_c[s ^ 1];
        if (tid == 0 && c_nxt < nchunks) {
            const int base = c_nxt * CHUNK_ELEMS;
            const uint32_t bytes = (uint32_t)min(CHUNK_ELEMS, n_total - base) * 4u;
            const uint32_t d = smem_u32(dynbuf) + (uint32_t)(s ^ 1) * STAGE_BYTES;
            const uint32_t m = smem_u32(&mb[s ^ 1]);
            mbar_expect_tx(m, 3u * bytes);
            bulk_g2s(d,                   pred  + base, bytes, m);
            bulk_g2s(d + CHUNK_BYTES,     label + base, bytes, m);
            bulk_g2s(d + 2 * CHUNK_BYTES, em    + base, bytes, m);
        }

        // wait + process current stage
        mbar_wait(smem_u32(&mb[s]), s ? phase1 : phase0);
        if (s) phase1 ^= 1; else phase0 ^= 1;

        const int base = c_cur * CHUNK_ELEMS;
        const int ce4  = min(CHUNK_ELEMS, n_total - base) >> 2;   // <=256
        // chunk lies in ONE channel block (1024 | 2^18): c = (base>>18)&15
        const float w = sWl[(c_cur >> 8) & 15];
        const char* stg = dynbuf + s * STAGE_BYTES;
        const float4* ps = (const float4*)(stg);
        const int4*   ls = (const int4*)  (stg + CHUNK_BYTES);
        const float4* es = (const float4*)(stg + 2 * CHUNK_BYTES);

        if (tid < ce4) {
            float4 p = ps[tid];
            int4   l = ls[tid];
            float4 e = es[tid];
            float t = 0.0f;
            if (l.x == 1) t += __logf(p.x + EPS) * e.x;
            if (l.y == 1) t += __logf(p.y + EPS) * e.y;
            if (l.z == 1) t += __logf(p.z + EPS) * e.z;
            if (l.w == 1) t += __logf(p.w + EPS) * e.w;
            acc = fmaf(-w, t, acc);
        }
        __syncthreads();   // stage s fully consumed before its re-arm next iter
        c_cur = c_nxt;
        s ^= 1;
    }

    // block reduce
    #pragma unroll
    for (int o = 16; o > 0; o >>= 1)
        acc += __shfl_xor_sync(0xffffffff, acc, o);

    const int lane = tid & 31;
    const int wid  = tid >> 5;
    if (lane == 0) red[wid] = acc;
    __syncthreads();
    if (wid == 0) {
        acc = (lane < 8) ? red[lane] : 0.0f;
        #pragma unroll
        for (int o = 4; o > 0; o >>= 1)
            acc += __shfl_xor_sync(0xffffffff, acc, o);
        if (lane == 0) atomicAdd(&g_acc, acc);
    }
    __syncthreads();

    // single release-atomic arrival per block; RMW chain publishes all g_acc adds
    if (tid == 0) {
        unsigned int old;
        asm volatile("atom.acq_rel.gpu.global.add.u32 %0, [%1], %2;"
                     : "=r"(old) : "l"(&g_count), "r"(1u) : "memory");
        s_last = (old == gridDim.x - 1);
    }
    __syncthreads();
    if (!s_last) return;

    if (tid == 0) {
        float tot;
        asm volatile("ld.acquire.gpu.global.f32 %0, [%1];"
                     : "=f"(tot) : "l"(&g_acc) : "memory");
        float su = 0.0f;
        for (int k = 0; k < n_ls; ++k) su += label_sum[k];
        out[0] = tot / su;
        g_acc   = 0.0f;   // deterministic reset for next graph replay
        g_count = 0u;
        g_chunk = 0u;     // every block's last grab precedes its arrival atomic
    }
}

extern "C" void kernel_launch(void* const* d_in, const int* in_sizes, int n_in,
                              void* d_out, int out_size)
{
    // metadata order: pred(f32), label(i32), Wl(f32[16]), label_sum(f32[16]), existmap(f32)
    const float* pred      = (const float*)d_in[0];
    const int*   label     = (const int*)  d_in[1];
    const float* Wl        = (const float*)d_in[2];
    const float* label_sum = (const float*)d_in[3];
    const float* em        = (const float*)d_in[4];
    float* out = (float*)d_out;

    const int n_total = in_sizes[0];

    const int threads = 256;
    int blocks = 1184;   // 8 CTAs/SM x 148 SMs; 24KB dyn smem each (192KB/SM)
    const int nchunks = (n_total + CHUNK_ELEMS - 1) / CHUNK_ELEMS;
    if (blocks > nchunks) blocks = nchunks;
    if (blocks < 1) blocks = 1;

    elc_tma_kernel<<<blocks, threads, 2 * STAGE_BYTES>>>(
        pred, label, Wl, label_sum, em, n_total, in_sizes[3], out);
}

// round 16
// speedup vs baseline: 1.1999x; 1.1999x over previous
#include <cuda_runtime.h>
#include <cuda_bf16.h>

#define EPS 0.01f

__device__ float g_acc = 0.0f;          // reset by last block each run
__device__ unsigned int g_count = 0;    // reset by last block each run

__global__ void __launch_bounds__(256, 8)   // 32 regs, 8 CTAs/SM (2048 thr/SM)
elc_fused_kernel(const float4* __restrict__ pred4,
                 const int4*   __restrict__ label4,
                 const float*  __restrict__ Wl,
                 const float*  __restrict__ label_sum,
                 const float4* __restrict__ em4,
                 int n4, int n_ls, int nblocks,
                 float* __restrict__ out)
{
    __shared__ float sWl[16];
    if (threadIdx.x < 16) sWl[threadIdx.x] = Wl[threadIdx.x];
    __syncthreads();

    float acc = 0.0f;
    const int nthreads = gridDim.x * blockDim.x;
    const int gid      = blockIdx.x * blockDim.x + threadIdx.x;
    const int npairs   = n4 >> 1;   // n4 even

    // R11's proven loop: 2 consecutive float4 per stream, 6 LDG.128
    // back-to-back -> warp presents 1KB contiguous per stream (DRAM row hits).
    // __ldcs: streaming/evict-first — zero reuse, keep L2 replacement calm.
    for (int g = gid; g < npairs; g += nthreads) {
        const int i = g << 1;
        float4 p0 = __ldcs(&pred4[i]);
        float4 p1 = __ldcs(&pred4[i + 1]);
        int4   l0 = __ldcs(&label4[i]);
        int4   l1 = __ldcs(&label4[i + 1]);
        float4 e0 = __ldcs(&em4[i]);
        float4 e1 = __ldcs(&em4[i + 1]);

        // pair 2g,2g+1 shares one channel: c = (8g >> 18) & 15 = (g>>15)&15
        const float w = sWl[(g >> 15) & 15];

        float t = 0.0f;
        if (l0.x == 1) t += __logf(p0.x + EPS) * e0.x;
        if (l0.y == 1) t += __logf(p0.y + EPS) * e0.y;
        if (l0.z == 1) t += __logf(p0.z + EPS) * e0.z;
        if (l0.w == 1) t += __logf(p0.w + EPS) * e0.w;
        if (l1.x == 1) t += __logf(p1.x + EPS) * e1.x;
        if (l1.y == 1) t += __logf(p1.y + EPS) * e1.y;
        if (l1.z == 1) t += __logf(p1.z + EPS) * e1.z;
        if (l1.w == 1) t += __logf(p1.w + EPS) * e1.w;
        acc = fmaf(-w, t, acc);
    }

    // block reduce
    #pragma unroll
    for (int o = 16; o > 0; o >>= 1)
        acc += __shfl_xor_sync(0xffffffff, acc, o);

    __shared__ float red[8];
    const int lane = threadIdx.x & 31;
    const int wid  = threadIdx.x >> 5;
    if (lane == 0) red[wid] = acc;
    __syncthreads();
    if (wid == 0) {
        acc = (lane < (blockDim.x >> 5)) ? red[lane] : 0.0f;
        #pragma unroll
        for (int o = 4; o > 0; o >>= 1)
            acc += __shfl_xor_sync(0xffffffff, acc, o);
        if (lane == 0) atomicAdd(&g_acc, acc);   // device-scope atomic
    }
    __syncthreads();

    // arrival: ONE release-atomic per block (thread 0); RMW chain on g_count
    // makes all g_acc adds visible to the final acquirer. No per-thread fences.
    __shared__ bool s_last;
    if (threadIdx.x == 0) {
        unsigned int old;
        asm volatile("atom.acq_rel.gpu.global.add.u32 %0, [%1], %2;"
                     : "=r"(old) : "l"(&g_count), "r"(1u) : "memory");
        s_last = (old == (unsigned int)nblocks - 1u);
    }
    __syncthreads();
    if (!s_last) return;

    if (threadIdx.x == 0) {
        float tot;
        asm volatile("ld.acquire.gpu.global.f32 %0, [%1];"
                     : "=f"(tot) : "l"(&g_acc) : "memory");
        float s = 0.0f;
        for (int k = 0; k < n_ls; ++k) s += label_sum[k];
        out[0] = tot / s;
        g_acc   = 0.0f;   // reset for next graph replay (deterministic)
        g_count = 0u;
    }
}

extern "C" void kernel_launch(void* const* d_in, const int* in_sizes, int n_in,
                              void* d_out, int out_size)
{
    // metadata order: pred(f32), label(i32), Wl(f32[16]), label_sum(f32[16]), existmap(f32)
    const float* pred      = (const float*)d_in[0];
    const int*   label     = (const int*)  d_in[1];
    const float* Wl        = (const float*)d_in[2];
    const float* label_sum = (const float*)d_in[3];
    const float* em        = (const float*)d_in[4];
    float* out = (float*)d_out;

    const int n_total = in_sizes[0];
    const int n4 = n_total >> 2;   // 8.39M float4s (even)

    const int threads = 256;
    int blocks = 4736;   // 4 waves x 8 CTAs/SM x 148 SMs
    int max_blocks = ((n4 >> 1) + threads - 1) / threads;
    if (blocks > max_blocks) blocks = max_blocks;
    if (blocks < 1) blocks = 1;

    elc_fused_kernel<<<blocks, threads>>>(
        (const float4*)pred, (const int4*)label, Wl, label_sum,
        (const float4*)em, n4, in_sizes[3], blocks, out);
}

// round 17
// speedup vs baseline: 1.2115x; 1.0097x over previous
#include <cuda_runtime.h>
#include <cuda_bf16.h>

#define EPS 0.01f

__device__ float g_acc = 0.0f;          // reset by last block each run
__device__ unsigned int g_count = 0;    // reset by last block each run

__global__ void __launch_bounds__(256, 8)   // 32 regs, 8 CTAs/SM (2048 thr/SM, RF-full)
elc_fused_kernel(const float4* __restrict__ pred4,
                 const int4*   __restrict__ label4,
                 const float*  __restrict__ Wl,
                 const float*  __restrict__ label_sum,
                 const float4* __restrict__ em4,
                 int n4, int n_ls, int nblocks,
                 float* __restrict__ out)
{
    __shared__ float sWl[16];
    if (threadIdx.x < 16) sWl[threadIdx.x] = Wl[threadIdx.x];
    __syncthreads();

    float acc = 0.0f;
    const int nthreads = gridDim.x * blockDim.x;
    const int gid      = blockIdx.x * blockDim.x + threadIdx.x;
    const int npairs   = n4 >> 1;   // n4 even

    // Champion loop (R11): 2 consecutive float4 per stream, 6 LDG.128
    // back-to-back -> each warp presents 1KB contiguous per stream
    // (maximizes DRAM row-hit runs at the measured ~6.34 TB/s ceiling).
    for (int g = gid; g < npairs; g += nthreads) {
        const int i = g << 1;
        float4 p0 = pred4[i];
        float4 p1 = pred4[i + 1];
        int4   l0 = label4[i];
        int4   l1 = label4[i + 1];
        float4 e0 = em4[i];
        float4 e1 = em4[i + 1];

        // pair 2g,2g+1 shares one channel: c = (8g >> 18) & 15 = (g>>15)&15
        const float w = sWl[(g >> 15) & 15];

        float t = 0.0f;
        if (l0.x == 1) t += __logf(p0.x + EPS) * e0.x;
        if (l0.y == 1) t += __logf(p0.y + EPS) * e0.y;
        if (l0.z == 1) t += __logf(p0.z + EPS) * e0.z;
        if (l0.w == 1) t += __logf(p0.w + EPS) * e0.w;
        if (l1.x == 1) t += __logf(p1.x + EPS) * e1.x;
        if (l1.y == 1) t += __logf(p1.y + EPS) * e1.y;
        if (l1.z == 1) t += __logf(p1.z + EPS) * e1.z;
        if (l1.w == 1) t += __logf(p1.w + EPS) * e1.w;
        acc = fmaf(-w, t, acc);
    }

    // block reduce
    #pragma unroll
    for (int o = 16; o > 0; o >>= 1)
        acc += __shfl_xor_sync(0xffffffff, acc, o);

    __shared__ float red[8];
    const int lane = threadIdx.x & 31;
    const int wid  = threadIdx.x >> 5;
    if (lane == 0) red[wid] = acc;
    __syncthreads();
    if (wid == 0) {
        acc = (lane < (blockDim.x >> 5)) ? red[lane] : 0.0f;
        #pragma unroll
        for (int o = 4; o > 0; o >>= 1)
            acc += __shfl_xor_sync(0xffffffff, acc, o);
        if (lane == 0) atomicAdd(&g_acc, acc);   // device-scope atomic
    }
    __syncthreads();

    // arrival: ONE release-atomic per block (thread 0); the RMW chain on
    // g_count makes every block's g_acc add visible to the final acquirer.
    // No per-thread fences anywhere on the hot path.
    __shared__ bool s_last;
    if (threadIdx.x == 0) {
        unsigned int old;
        asm volatile("atom.acq_rel.gpu.global.add.u32 %0, [%1], %2;"
                     : "=r"(old) : "l"(&g_count), "r"(1u) : "memory");
        s_last = (old == (unsigned int)nblocks - 1u);
    }
    __syncthreads();
    if (!s_last) return;

    if (threadIdx.x == 0) {
        float tot;
        asm volatile("ld.acquire.gpu.global.f32 %0, [%1];"
                     : "=f"(tot) : "l"(&g_acc) : "memory");
        float s = 0.0f;
        for (int k = 0; k < n_ls; ++k) s += label_sum[k];
        out[0] = tot / s;
        g_acc   = 0.0f;   // reset for next graph replay (deterministic)
        g_count = 0u;
    }
}

extern "C" void kernel_launch(void* const* d_in, const int* in_sizes, int n_in,
                              void* d_out, int out_size)
{
    // metadata order: pred(f32), label(i32), Wl(f32[16]), label_sum(f32[16]), existmap(f32)
    const float* pred      = (const float*)d_in[0];
    const int*   label     = (const int*)  d_in[1];
    const float* Wl        = (const float*)d_in[2];
    const float* label_sum = (const float*)d_in[3];
    const float* em        = (const float*)d_in[4];
    float* out = (float*)d_out;

    const int n_total = in_sizes[0];
    const int n4 = n_total >> 2;   // 8.39M float4s (even)

    const int threads = 256;
    int blocks = 4736;   // 4 waves x 8 CTAs/SM x 148 SMs
    int max_blocks = ((n4 >> 1) + threads - 1) / threads;
    if (blocks > max_blocks) blocks = max_blocks;
    if (blocks < 1) blocks = 1;

    elc_fused_kernel<<<blocks, threads>>>(
        (const float4*)pred, (const int4*)label, Wl, label_sum,
        (const float4*)em, n4, in_sizes[3], blocks, out);
}